// round 8
// baseline (speedup 1.0000x reference)
#include <cuda_runtime.h>
#include <cstdint>

#define BATCH 256
#define NSRC  10
#define NMC_C 16
#define LL_C  128
#define PLANE (LL_C * LL_C)                // 16384 floats
#define PLANE4 (PLANE / 4)                 // 4096 float4
#define TPB   256
#define K_PER_PLANE (PLANE4 / TPB)         // 16 float4 stores per thread per plane

// grid = BATCH*4 = 1024 blocks, one wave, identical work per block.
// Block blk: batch b = blk>>2, mass-bin quarter q = blk&3.
// Writes 8 planes: channels {4q..4q+3} (ones half, override->0)
//              and {16+4q..16+4q+3} (zeros half, override->1).
__global__ void __launch_bounds__(TPB, 8) fused_kernel(
    const float* __restrict__ coord,
    const float* __restrict__ lows,
    const float* __restrict__ highs,
    float* __restrict__ out)
{
    __shared__ int s_cnt[4];
    __shared__ int s_offs[4][NSRC];

    int blk = blockIdx.x;
    int b   = blk >> 2;
    int q   = blk & 3;
    int t   = threadIdx.x;

    if (t < 4) s_cnt[t] = 0;
    __syncthreads();

    // --- per-block point computation (threads 0..9, once for 8 planes) ---
    if (t < NSRC) {
        const float* c = coord + (size_t)b * (3 * NSRC) + t * 3;
        float lo0 = lows[0], lo1 = lows[1], lo2 = lows[2];
        float hi0 = highs[0], hi1 = highs[1], hi2 = highs[2];

        float xg = (c[0]         - lo0) / (hi0 - lo0);
        float yg = (c[1]         - lo1) / (hi1 - lo1);
        float mg = (log10f(c[2]) - lo2) / (hi2 - lo2);

        int xi = (int)floorf(xg * (float)LL_C);
        int yi = (int)floorf(yg * (float)LL_C);
        int mi = (int)floorf(mg * (float)NMC_C);

        bool ok = ((unsigned)xi < LL_C) & ((unsigned)yi < LL_C) &
                  ((unsigned)mi < NMC_C) & ((mi >> 2) == q);
        if (ok) {
            int slot = atomicAdd(&s_cnt[mi & 3], 1);
            s_offs[mi & 3][slot] = yi * LL_C + xi;
        }
    }
    __syncthreads();

    float* outb = out + (size_t)b * (2 * NMC_C) * PLANE;

#pragma unroll
    for (int m = 0; m < 4; m++) {
        int cnt = s_cnt[m];
        float4* p1 = (float4*)(outb + (size_t)(4 * q + m) * PLANE);          // ones
        float4* p2 = (float4*)(outb + (size_t)(NMC_C + 4 * q + m) * PLANE);  // zeros

        if (cnt == 0) {
            float4 one4  = make_float4(1.f, 1.f, 1.f, 1.f);
            float4 zero4 = make_float4(0.f, 0.f, 0.f, 0.f);
#pragma unroll
            for (int k = 0; k < K_PER_PLANE; k++)
                p1[t + k * TPB] = one4;
#pragma unroll
            for (int k = 0; k < K_PER_PLANE; k++)
                p2[t + k * TPB] = zero4;
        } else {
#pragma unroll
            for (int k = 0; k < K_PER_PLANE; k++) {
                int base4 = t + k * TPB;
                float4 v1 = make_float4(1.f, 1.f, 1.f, 1.f);
                float4 v2 = make_float4(0.f, 0.f, 0.f, 0.f);
                for (int j = 0; j < cnt; j++) {
                    int o = s_offs[m][j];
                    if ((o >> 2) == base4) {
                        ((float*)&v1)[o & 3] = 0.f;
                        ((float*)&v2)[o & 3] = 1.f;
                    }
                }
                p1[base4] = v1;
                p2[base4] = v2;
            }
        }
    }
}

extern "C" void kernel_launch(void* const* d_in, const int* in_sizes, int n_in,
                              void* d_out, int out_size) {
    const float* coord = (const float*)d_in[0];
    const float* lows  = (const float*)d_in[1];
    const float* highs = (const float*)d_in[2];
    float* out = (float*)d_out;

    fused_kernel<<<BATCH * 4, TPB>>>(coord, lows, highs, out);
}